// round 2
// baseline (speedup 1.0000x reference)
#include <cuda_runtime.h>

#define BB   8
#define NN   9225
#define MM   4096
#define KNB  32
#define HID  64
#define DOUT 16

__device__ int g_idx_is64;

// Detect whether neighbors_index is int64 or int32.
// If int64: every high 32-bit word is 0 (idx in [0,9225)) or -1 (padded).
// If int32: "high words" are themselves random indices -> almost surely neither.
__global__ void detect_idx_width_kernel(const int* __restrict__ nbr) {
    bool is64 = true;
    #pragma unroll 1
    for (int i = 0; i < 64; i++) {
        int hi = nbr[2 * i + 1];
        if (hi != 0 && hi != -1) { is64 = false; break; }
    }
    g_idx_is64 = is64 ? 1 : 0;
}

__global__ __launch_bounds__(256) void it_kernel(
    const float* __restrict__ y,     // [B,N,2]
    const float* __restrict__ x,     // [B,M,2]
    const float* __restrict__ f_y,   // [B,N,16]
    const float* __restrict__ wts,   // [B,N]
    const float* __restrict__ W1,    // [4,64]
    const float* __restrict__ b1,    // [64]
    const float* __restrict__ W2,    // [64,16]
    const float* __restrict__ b2,    // [16]
    const void*  __restrict__ nbr,   // [B,M,32] int64 or int32
    float* __restrict__ out)         // [B,M,16]
{
    __shared__ float sW1[HID][4];    // transposed: sW1[j][i] = W1[i][j]
    __shared__ float sb1[HID];
    __shared__ float sW2[HID][DOUT]; // row-major, rows 64B -> float4 loads
    __shared__ float sb2[DOUT];

    const int tid = threadIdx.x;
    {
        int i = tid >> 6;            // 0..3
        int j = tid & 63;
        sW1[j][i] = W1[i * HID + j];
        if (tid < HID) sb1[tid] = b1[tid];
        for (int t = tid; t < HID * DOUT; t += 256)
            (&sW2[0][0])[t] = W2[t];
        if (tid < DOUT) sb2[tid] = b2[tid];
    }
    __syncthreads();

    const int warp = (blockIdx.x << 3) + (tid >> 5);   // global (b,m) id, 256 thr = 8 warps
    const int lane = tid & 31;
    const int b = warp / MM;
    // warp == b*MM + m directly indexes [B,M,...] arrays

    // ---- gather inputs ----
    const bool is64 = (g_idx_is64 != 0);
    long long raw;
    if (is64) raw = ((const long long*)nbr)[(size_t)warp * KNB + lane];
    else      raw = (long long)((const int*)nbr)[(size_t)warp * KNB + lane];
    const bool valid = (raw >= 0);
    const int idx = valid ? (int)raw : 0;

    const float2 yy = ((const float2*)y)[(size_t)b * NN + idx];
    const float2 xx = ((const float2*)x)[warp];
    const float a0 = yy.x, a1 = yy.y, a2 = xx.x, a3 = xx.y;
    const float s = valid ? wts[(size_t)b * NN + idx] : 0.0f;

    // ---- MLP: 4 -> 64 -> gelu -> 16 ----
    float acc[DOUT];
    #pragma unroll
    for (int c = 0; c < DOUT; c++) acc[c] = 0.0f;

    #pragma unroll 8
    for (int j = 0; j < HID; j++) {
        float h = sb1[j];
        h = fmaf(a0, sW1[j][0], h);
        h = fmaf(a1, sW1[j][1], h);
        h = fmaf(a2, sW1[j][2], h);
        h = fmaf(a3, sW1[j][3], h);
        // exact gelu: 0.5*h*(1+erf(h/sqrt(2)))
        const float g = 0.5f * h * (1.0f + erff(h * 0.70710678118654752f));
        const float4* w2r = (const float4*)&sW2[j][0];
        #pragma unroll
        for (int q = 0; q < 4; q++) {
            float4 w = w2r[q];
            acc[4 * q + 0] = fmaf(g, w.x, acc[4 * q + 0]);
            acc[4 * q + 1] = fmaf(g, w.y, acc[4 * q + 1]);
            acc[4 * q + 2] = fmaf(g, w.z, acc[4 * q + 2]);
            acc[4 * q + 3] = fmaf(g, w.w, acc[4 * q + 3]);
        }
    }

    // ---- scale by f_y[idx] * w[idx] * valid (loaded late to cut reg pressure) ----
    const float4* fyp = (const float4*)(f_y + ((size_t)b * NN + idx) * DOUT);
    #pragma unroll
    for (int q = 0; q < 4; q++) {
        float4 fy = fyp[q];
        acc[4 * q + 0] = (acc[4 * q + 0] + sb2[4 * q + 0]) * fy.x * s;
        acc[4 * q + 1] = (acc[4 * q + 1] + sb2[4 * q + 1]) * fy.y * s;
        acc[4 * q + 2] = (acc[4 * q + 2] + sb2[4 * q + 2]) * fy.z * s;
        acc[4 * q + 3] = (acc[4 * q + 3] + sb2[4 * q + 3]) * fy.w * s;
    }

    // ---- warp butterfly reduce over K=32 neighbors ----
    #pragma unroll
    for (int off = 16; off >= 1; off >>= 1) {
        #pragma unroll
        for (int c = 0; c < DOUT; c++)
            acc[c] += __shfl_xor_sync(0xffffffffu, acc[c], off);
    }

    if (lane < DOUT)
        out[(size_t)warp * DOUT + lane] = acc[lane];
}

extern "C" void kernel_launch(void* const* d_in, const int* in_sizes, int n_in,
                              void* d_out, int out_size) {
    const float* y   = (const float*)d_in[0];
    const float* x   = (const float*)d_in[1];
    const float* f_y = (const float*)d_in[2];
    const float* wts = (const float*)d_in[3];
    const float* W1  = (const float*)d_in[4];
    const float* b1  = (const float*)d_in[5];
    const float* W2  = (const float*)d_in[6];
    const float* b2  = (const float*)d_in[7];
    const void*  nbr = d_in[8];

    detect_idx_width_kernel<<<1, 1>>>((const int*)nbr);
    // one warp per (b,m): 8*4096 = 32768 warps -> 4096 blocks of 256 threads
    it_kernel<<<4096, 256>>>(y, x, f_y, wts, W1, b1, W2, b2, nbr, (float*)d_out);
}

// round 3
// speedup vs baseline: 1.1365x; 1.1365x over previous
#include <cuda_runtime.h>

#define BB   8
#define NN   9225
#define MM   4096
#define KNB  32
#define HID  64
#define DOUT 16

__device__ int g_idx_is64;

// Detect whether neighbors_index is int64 or int32.
// int64: every high 32-bit word is 0 (idx in [0,9225)) or -1 (padded).
__global__ void detect_idx_width_kernel(const int* __restrict__ nbr) {
    bool is64 = true;
    #pragma unroll 1
    for (int i = 0; i < 64; i++) {
        int hi = nbr[2 * i + 1];
        if (hi != 0 && hi != -1) { is64 = false; break; }
    }
    g_idx_is64 = is64 ? 1 : 0;
}

// ---- packed f32x2 helpers (sm_103a FFMA2 path, PTX-only) ----
__device__ __forceinline__ unsigned long long fmax2(unsigned long long a,
                                                    unsigned long long b,
                                                    unsigned long long c) {
    unsigned long long r;
    asm("fma.rn.f32x2 %0, %1, %2, %3;" : "=l"(r) : "l"(a), "l"(b), "l"(c));
    return r;
}
__device__ __forceinline__ unsigned long long addx2(unsigned long long a,
                                                    unsigned long long b) {
    unsigned long long r;
    asm("add.rn.f32x2 %0, %1, %2;" : "=l"(r) : "l"(a), "l"(b));
    return r;
}
__device__ __forceinline__ unsigned long long mulx2(unsigned long long a,
                                                    unsigned long long b) {
    unsigned long long r;
    asm("mul.rn.f32x2 %0, %1, %2;" : "=l"(r) : "l"(a), "l"(b));
    return r;
}
__device__ __forceinline__ unsigned long long pack2(float lo, float hi) {
    unsigned long long r;
    asm("mov.b64 %0, {%1, %2};" : "=l"(r) : "f"(lo), "f"(hi));
    return r;
}
__device__ __forceinline__ void unpack2(unsigned long long v, float& lo, float& hi) {
    asm("mov.b64 {%0, %1}, %2;" : "=f"(lo), "=f"(hi) : "l"(v));
}
__device__ __forceinline__ unsigned long long shfl64(unsigned long long v, int off) {
    return __shfl_xor_sync(0xffffffffu, v, off);
}

__global__ __launch_bounds__(256) void it_kernel(
    const float* __restrict__ y,     // [B,N,2]
    const float* __restrict__ x,     // [B,M,2]
    const float* __restrict__ f_y,   // [B,N,16]
    const float* __restrict__ wts,   // [B,N]
    const float* __restrict__ W1,    // [4,64]
    const float* __restrict__ b1,    // [64]
    const float* __restrict__ W2,    // [64,16]
    const float* __restrict__ b2,    // [16]
    const void*  __restrict__ nbr,   // [B,M,32] int64 or int32
    float* __restrict__ out)         // [B,M,16]
{
    // per-warp layer-1 table: {W1[0][j], W1[1][j], c_j, 0} with
    // c_j = b1[j] + x0*W1[2][j] + x1*W1[3][j]   (x is warp-uniform)
    __shared__ __align__(16) float4 sL1[8][HID];        // 8 KB
    __shared__ __align__(16) float  sW2[HID][DOUT];     // 4 KB
    __shared__ __align__(16) float  sb2[DOUT];

    const int tid  = threadIdx.x;
    const int wb   = tid >> 5;                 // warp in block
    const int lane = tid & 31;
    const int warp = (blockIdx.x << 3) + wb;   // global (b,m) id
    const int b    = warp / MM;

    // stage W2 / b2
    for (int t = tid; t < HID * DOUT; t += 256)
        (&sW2[0][0])[t] = W2[t];
    if (tid < DOUT) sb2[tid] = b2[tid];

    // ---- per-lane gather ----
    const bool is64 = (g_idx_is64 != 0);
    long long raw;
    if (is64) raw = ((const long long*)nbr)[(size_t)warp * KNB + lane];
    else      raw = (long long)((const int*)nbr)[(size_t)warp * KNB + lane];
    const bool valid = (raw >= 0);
    const int idx = valid ? (int)raw : 0;

    const float2 yy = ((const float2*)y)[(size_t)b * NN + idx];
    const float2 xx = ((const float2*)x)[warp];
    const float a0 = yy.x, a1 = yy.y;
    const float s = valid ? wts[(size_t)b * NN + idx] : 0.0f;

    // ---- build per-warp layer-1 table (2 j's per lane) ----
    {
        const float a2 = xx.x, a3 = xx.y;
        #pragma unroll
        for (int t = 0; t < 2; t++) {
            int j = lane + 32 * t;
            float w0 = W1[j];
            float w1 = W1[HID + j];
            float w2 = W1[2 * HID + j];
            float w3 = W1[3 * HID + j];
            float c  = fmaf(a3, w3, fmaf(a2, w2, b1[j]));
            sL1[wb][j] = make_float4(w0, w1, c, 0.0f);
        }
    }
    __syncthreads();   // covers sW2/sb2 and sL1

    // ---- MLP mainloop: 64 hidden units, packed layer-2 ----
    unsigned long long acc2[8];
    #pragma unroll
    for (int p = 0; p < 8; p++) acc2[p] = 0ull;   // {0.f,0.f}

    #pragma unroll 4
    for (int j = 0; j < HID; j++) {
        float4 v = sL1[wb][j];
        float h = fmaf(a0, v.x, fmaf(a1, v.y, v.z));
        float e = erff(h * 0.70710678118654752f);
        float g = h * fmaf(0.5f, e, 0.5f);        // exact gelu
        unsigned long long gg = pack2(g, g);
        const ulonglong2* w2p = (const ulonglong2*)&sW2[j][0];
        ulonglong2 wA = w2p[0], wB = w2p[1], wC = w2p[2], wD = w2p[3];
        acc2[0] = fmax2(gg, wA.x, acc2[0]);
        acc2[1] = fmax2(gg, wA.y, acc2[1]);
        acc2[2] = fmax2(gg, wB.x, acc2[2]);
        acc2[3] = fmax2(gg, wB.y, acc2[3]);
        acc2[4] = fmax2(gg, wC.x, acc2[4]);
        acc2[5] = fmax2(gg, wC.y, acc2[5]);
        acc2[6] = fmax2(gg, wD.x, acc2[6]);
        acc2[7] = fmax2(gg, wD.y, acc2[7]);
    }

    // ---- epilogue scale: (acc + b2) * f_y[idx] * w[idx] * valid, packed ----
    {
        const ulonglong2* fyp = (const ulonglong2*)(f_y + ((size_t)b * NN + idx) * DOUT);
        const ulonglong2* b2p = (const ulonglong2*)sb2;
        unsigned long long ss = pack2(s, s);
        #pragma unroll
        for (int q = 0; q < 4; q++) {
            ulonglong2 fy = fyp[q];
            ulonglong2 bq = b2p[q];
            acc2[2 * q + 0] = mulx2(mulx2(addx2(acc2[2 * q + 0], bq.x), fy.x), ss);
            acc2[2 * q + 1] = mulx2(mulx2(addx2(acc2[2 * q + 1], bq.y), fy.y), ss);
        }
    }

    // ---- channel-splitting warp reduce (16 ch over 32 lanes) ----
    // round A: off=16, pairs 0-3 vs 4-7
    {
        bool hi = (lane & 16) != 0;
        #pragma unroll
        for (int p = 0; p < 4; p++) {
            unsigned long long send = hi ? acc2[p]     : acc2[p + 4];
            unsigned long long keep = hi ? acc2[p + 4] : acc2[p];
            acc2[p] = addx2(keep, shfl64(send, 16));
        }
    }
    // round B: off=8, pairs 0-1 vs 2-3
    {
        bool hi = (lane & 8) != 0;
        #pragma unroll
        for (int p = 0; p < 2; p++) {
            unsigned long long send = hi ? acc2[p]     : acc2[p + 2];
            unsigned long long keep = hi ? acc2[p + 2] : acc2[p];
            acc2[p] = addx2(keep, shfl64(send, 8));
        }
    }
    // round C: off=4, pair 0 vs 1
    {
        bool hi = (lane & 4) != 0;
        unsigned long long send = hi ? acc2[0] : acc2[1];
        unsigned long long keep = hi ? acc2[1] : acc2[0];
        acc2[0] = addx2(keep, shfl64(send, 4));
    }
    // round D: off=2, split the pair into scalars
    float r;
    {
        float lo, hv;
        unpack2(acc2[0], lo, hv);
        bool hi = (lane & 2) != 0;
        float send = hi ? lo : hv;
        float keep = hi ? hv : lo;
        r = keep + __shfl_xor_sync(0xffffffffu, send, 2);
    }
    // round E: off=1
    r += __shfl_xor_sync(0xffffffffu, r, 1);

    // channel bits [3..0] = lane bits [4..1]; both lanes of each odd/even
    // pair hold the full sum -> store from even lanes.
    if ((lane & 1) == 0)
        out[(size_t)warp * DOUT + (lane >> 1)] = r;
}

extern "C" void kernel_launch(void* const* d_in, const int* in_sizes, int n_in,
                              void* d_out, int out_size) {
    const float* y   = (const float*)d_in[0];
    const float* x   = (const float*)d_in[1];
    const float* f_y = (const float*)d_in[2];
    const float* wts = (const float*)d_in[3];
    const float* W1  = (const float*)d_in[4];
    const float* b1  = (const float*)d_in[5];
    const float* W2  = (const float*)d_in[6];
    const float* b2  = (const float*)d_in[7];
    const void*  nbr = d_in[8];

    detect_idx_width_kernel<<<1, 1>>>((const int*)nbr);
    it_kernel<<<4096, 256>>>(y, x, f_y, wts, W1, b1, W2, b2, nbr, (float*)d_out);
}

// round 4
// speedup vs baseline: 1.2155x; 1.0695x over previous
#include <cuda_runtime.h>

#define BB   8
#define NN   9225
#define MM   4096
#define KNB  32
#define HID  64
#define DOUT 16

__device__ int g_idx_is64;

// Detect whether neighbors_index is int64 or int32 (branch-free: loads overlap).
__global__ void detect_idx_width_kernel(const int* __restrict__ nbr) {
    int bad = 0;
    #pragma unroll
    for (int i = 0; i < 64; i++) {
        int hi = nbr[2 * i + 1];
        bad |= (hi != 0 && hi != -1);
    }
    g_idx_is64 = bad ? 0 : 1;
}

// ---- packed f32x2 helpers (sm_103a FFMA2 path, PTX-only) ----
__device__ __forceinline__ unsigned long long fmax2(unsigned long long a,
                                                    unsigned long long b,
                                                    unsigned long long c) {
    unsigned long long r;
    asm("fma.rn.f32x2 %0, %1, %2, %3;" : "=l"(r) : "l"(a), "l"(b), "l"(c));
    return r;
}
__device__ __forceinline__ unsigned long long addx2(unsigned long long a,
                                                    unsigned long long b) {
    unsigned long long r;
    asm("add.rn.f32x2 %0, %1, %2;" : "=l"(r) : "l"(a), "l"(b));
    return r;
}
__device__ __forceinline__ unsigned long long mulx2(unsigned long long a,
                                                    unsigned long long b) {
    unsigned long long r;
    asm("mul.rn.f32x2 %0, %1, %2;" : "=l"(r) : "l"(a), "l"(b));
    return r;
}
__device__ __forceinline__ unsigned long long pack2(float lo, float hi) {
    unsigned long long r;
    asm("mov.b64 %0, {%1, %2};" : "=l"(r) : "f"(lo), "f"(hi));
    return r;
}
__device__ __forceinline__ void unpack2(unsigned long long v, float& lo, float& hi) {
    asm("mov.b64 {%0, %1}, %2;" : "=f"(lo), "=f"(hi) : "l"(v));
}
__device__ __forceinline__ unsigned long long shfl64(unsigned long long v, int off) {
    return __shfl_xor_sync(0xffffffffu, v, off);
}
__device__ __forceinline__ float rcp_approx(float x) {
    float r;
    asm("rcp.approx.f32 %0, %1;" : "=f"(r) : "f"(x));
    return r;
}
__device__ __forceinline__ float ex2_approx(float x) {
    float r;
    asm("ex2.approx.f32 %0, %1;" : "=f"(r) : "f"(x));
    return r;
}

// Branchless exact-form gelu: 0.5*h*(1+erf(h/sqrt(2))),
// erf via Abramowitz-Stegun 7.1.26 (abs err <= 1.5e-7).
__device__ __forceinline__ float gelu_fast(float h) {
    const float a = fabsf(h) * 0.70710678118654752f;    // |x|
    const float d = fmaf(0.3275911f, a, 1.0f);
    const float t = rcp_approx(d);
    const float e = ex2_approx(a * a * -1.4426950408889634f);  // exp(-x^2)
    float p = fmaf(1.061405429f, t, -1.453152027f);
    p = fmaf(p, t, 1.421413741f);
    p = fmaf(p, t, -0.284496736f);
    p = fmaf(p, t, 0.254829592f);
    const float r = fmaf(-p * t, e, 1.0f);              // erf(|x|)
    const float hh = 0.5f * h;
    return fmaf(fabsf(hh), r, hh);                      // 0.5h + 0.5|h|*erf(|x|)
}

__global__ __launch_bounds__(256) void it_kernel(
    const float* __restrict__ y,     // [B,N,2]
    const float* __restrict__ x,     // [B,M,2]
    const float* __restrict__ f_y,   // [B,N,16]
    const float* __restrict__ wts,   // [B,N]
    const float* __restrict__ W1,    // [4,64]
    const float* __restrict__ b1,    // [64]
    const float* __restrict__ W2,    // [64,16]
    const float* __restrict__ b2,    // [16]
    const void*  __restrict__ nbr,   // [B,M,32] int64 or int32
    float* __restrict__ out)         // [B,M,16]
{
    // per-warp layer-1 table: {W1[0][j], W1[1][j], c_j, 0} with
    // c_j = b1[j] + x0*W1[2][j] + x1*W1[3][j]   (x is warp-uniform)
    __shared__ __align__(16) float4 sL1[8][HID];        // 8 KB
    __shared__ __align__(16) float  sW2[HID][DOUT];     // 4 KB
    __shared__ __align__(16) float  sb2[DOUT];

    const int tid  = threadIdx.x;
    const int wb   = tid >> 5;                 // warp in block
    const int lane = tid & 31;
    const int warp = (blockIdx.x << 3) + wb;   // global (b,m) id
    const int b    = warp / MM;

    // stage W2 / b2
    for (int t = tid; t < HID * DOUT; t += 256)
        (&sW2[0][0])[t] = W2[t];
    if (tid < DOUT) sb2[tid] = b2[tid];

    // ---- per-lane gather ----
    const bool is64 = (g_idx_is64 != 0);
    long long raw;
    if (is64) raw = ((const long long*)nbr)[(size_t)warp * KNB + lane];
    else      raw = (long long)((const int*)nbr)[(size_t)warp * KNB + lane];
    const bool valid = (raw >= 0);
    const int idx = valid ? (int)raw : 0;

    const float2 yy = ((const float2*)y)[(size_t)b * NN + idx];
    const float2 xx = ((const float2*)x)[warp];
    const float a0 = yy.x, a1 = yy.y;
    const float s = valid ? wts[(size_t)b * NN + idx] : 0.0f;

    // ---- build per-warp layer-1 table (2 j's per lane) ----
    {
        const float a2 = xx.x, a3 = xx.y;
        #pragma unroll
        for (int t = 0; t < 2; t++) {
            int j = lane + 32 * t;
            float w0 = W1[j];
            float w1 = W1[HID + j];
            float w2 = W1[2 * HID + j];
            float w3 = W1[3 * HID + j];
            float c  = fmaf(a3, w3, fmaf(a2, w2, b1[j]));
            sL1[wb][j] = make_float4(w0, w1, c, 0.0f);
        }
    }
    __syncthreads();   // covers sW2/sb2 and sL1

    // ---- MLP mainloop: 64 hidden units, packed layer-2 ----
    unsigned long long acc2[8];
    #pragma unroll
    for (int p = 0; p < 8; p++) acc2[p] = 0ull;   // {0.f,0.f}

    #pragma unroll 8
    for (int j = 0; j < HID; j++) {
        float4 v = sL1[wb][j];
        float h = fmaf(a0, v.x, fmaf(a1, v.y, v.z));
        float g = gelu_fast(h);
        unsigned long long gg = pack2(g, g);
        const ulonglong2* w2p = (const ulonglong2*)&sW2[j][0];
        ulonglong2 wA = w2p[0], wB = w2p[1], wC = w2p[2], wD = w2p[3];
        acc2[0] = fmax2(gg, wA.x, acc2[0]);
        acc2[1] = fmax2(gg, wA.y, acc2[1]);
        acc2[2] = fmax2(gg, wB.x, acc2[2]);
        acc2[3] = fmax2(gg, wB.y, acc2[3]);
        acc2[4] = fmax2(gg, wC.x, acc2[4]);
        acc2[5] = fmax2(gg, wC.y, acc2[5]);
        acc2[6] = fmax2(gg, wD.x, acc2[6]);
        acc2[7] = fmax2(gg, wD.y, acc2[7]);
    }

    // ---- epilogue scale: (acc + b2) * f_y[idx] * w[idx] * valid, packed ----
    {
        const ulonglong2* fyp = (const ulonglong2*)(f_y + ((size_t)b * NN + idx) * DOUT);
        const ulonglong2* b2p = (const ulonglong2*)sb2;
        unsigned long long ss = pack2(s, s);
        #pragma unroll
        for (int q = 0; q < 4; q++) {
            ulonglong2 fy = fyp[q];
            ulonglong2 bq = b2p[q];
            acc2[2 * q + 0] = mulx2(mulx2(addx2(acc2[2 * q + 0], bq.x), fy.x), ss);
            acc2[2 * q + 1] = mulx2(mulx2(addx2(acc2[2 * q + 1], bq.y), fy.y), ss);
        }
    }

    // ---- channel-splitting warp reduce (16 ch over 32 lanes) ----
    {
        bool hi = (lane & 16) != 0;
        #pragma unroll
        for (int p = 0; p < 4; p++) {
            unsigned long long send = hi ? acc2[p]     : acc2[p + 4];
            unsigned long long keep = hi ? acc2[p + 4] : acc2[p];
            acc2[p] = addx2(keep, shfl64(send, 16));
        }
    }
    {
        bool hi = (lane & 8) != 0;
        #pragma unroll
        for (int p = 0; p < 2; p++) {
            unsigned long long send = hi ? acc2[p]     : acc2[p + 2];
            unsigned long long keep = hi ? acc2[p + 2] : acc2[p];
            acc2[p] = addx2(keep, shfl64(send, 8));
        }
    }
    {
        bool hi = (lane & 4) != 0;
        unsigned long long send = hi ? acc2[0] : acc2[1];
        unsigned long long keep = hi ? acc2[1] : acc2[0];
        acc2[0] = addx2(keep, shfl64(send, 4));
    }
    float r;
    {
        float lo, hv;
        unpack2(acc2[0], lo, hv);
        bool hi = (lane & 2) != 0;
        float send = hi ? lo : hv;
        float keep = hi ? hv : lo;
        r = keep + __shfl_xor_sync(0xffffffffu, send, 2);
    }
    r += __shfl_xor_sync(0xffffffffu, r, 1);

    if ((lane & 1) == 0)
        out[(size_t)warp * DOUT + (lane >> 1)] = r;
}

extern "C" void kernel_launch(void* const* d_in, const int* in_sizes, int n_in,
                              void* d_out, int out_size) {
    const float* y   = (const float*)d_in[0];
    const float* x   = (const float*)d_in[1];
    const float* f_y = (const float*)d_in[2];
    const float* wts = (const float*)d_in[3];
    const float* W1  = (const float*)d_in[4];
    const float* b1  = (const float*)d_in[5];
    const float* W2  = (const float*)d_in[6];
    const float* b2  = (const float*)d_in[7];
    const void*  nbr = d_in[8];

    detect_idx_width_kernel<<<1, 1>>>((const int*)nbr);
    it_kernel<<<4096, 256>>>(y, x, f_y, wts, W1, b1, W2, b2, nbr, (float*)d_out);
}

// round 5
// speedup vs baseline: 1.3730x; 1.1296x over previous
#include <cuda_runtime.h>

#define BB   8
#define NN   9225
#define MM   4096
#define KNB  32
#define HID  64
#define DOUT 16

__device__ int g_idx_is64;

__constant__ __align__(16) float cW2[HID * DOUT];   // 4 KB
__constant__ __align__(16) float cb2[DOUT];

// Detect whether neighbors_index is int64 or int32 (branch-free: loads overlap).
__global__ void detect_idx_width_kernel(const int* __restrict__ nbr) {
    int bad = 0;
    #pragma unroll
    for (int i = 0; i < 64; i++) {
        int hi = nbr[2 * i + 1];
        bad |= (hi != 0 && hi != -1);
    }
    g_idx_is64 = bad ? 0 : 1;
}

// ---- packed f32x2 helpers (sm_103a FFMA2 path, PTX-only) ----
__device__ __forceinline__ unsigned long long fmax2(unsigned long long a,
                                                    unsigned long long b,
                                                    unsigned long long c) {
    unsigned long long r;
    asm("fma.rn.f32x2 %0, %1, %2, %3;" : "=l"(r) : "l"(a), "l"(b), "l"(c));
    return r;
}
__device__ __forceinline__ unsigned long long addx2(unsigned long long a,
                                                    unsigned long long b) {
    unsigned long long r;
    asm("add.rn.f32x2 %0, %1, %2;" : "=l"(r) : "l"(a), "l"(b));
    return r;
}
__device__ __forceinline__ unsigned long long mulx2(unsigned long long a,
                                                    unsigned long long b) {
    unsigned long long r;
    asm("mul.rn.f32x2 %0, %1, %2;" : "=l"(r) : "l"(a), "l"(b));
    return r;
}
__device__ __forceinline__ unsigned long long pack2(float lo, float hi) {
    unsigned long long r;
    asm("mov.b64 %0, {%1, %2};" : "=l"(r) : "f"(lo), "f"(hi));
    return r;
}
__device__ __forceinline__ void unpack2(unsigned long long v, float& lo, float& hi) {
    asm("mov.b64 {%0, %1}, %2;" : "=f"(lo), "=f"(hi) : "l"(v));
}
__device__ __forceinline__ unsigned long long shfl64(unsigned long long v, int off) {
    return __shfl_xor_sync(0xffffffffu, v, off);
}
__device__ __forceinline__ float rcp_approx(float x) {
    float r;
    asm("rcp.approx.f32 %0, %1;" : "=f"(r) : "f"(x));
    return r;
}
__device__ __forceinline__ float ex2_approx(float x) {
    float r;
    asm("ex2.approx.f32 %0, %1;" : "=f"(r) : "f"(x));
    return r;
}

// Branchless exact-form gelu: 0.5*h*(1+erf(h/sqrt(2))),
// erf via Abramowitz-Stegun 7.1.26 (abs err <= 1.5e-7).
__device__ __forceinline__ float gelu_fast(float h) {
    const float a = fabsf(h) * 0.70710678118654752f;
    const float d = fmaf(0.3275911f, a, 1.0f);
    const float t = rcp_approx(d);
    const float e = ex2_approx(a * a * -1.4426950408889634f);
    float p = fmaf(1.061405429f, t, -1.453152027f);
    p = fmaf(p, t, 1.421413741f);
    p = fmaf(p, t, -0.284496736f);
    p = fmaf(p, t, 0.254829592f);
    const float r = fmaf(-p * t, e, 1.0f);
    const float hh = 0.5f * h;
    return fmaf(fabsf(hh), r, hh);
}

__global__ __launch_bounds__(256) void it_kernel(
    const float* __restrict__ y,     // [B,N,2]
    const float* __restrict__ x,     // [B,M,2]
    const float* __restrict__ f_y,   // [B,N,16]
    const float* __restrict__ wts,   // [B,N]
    const float* __restrict__ W1,    // [4,64]
    const float* __restrict__ b1,    // [64]
    const void*  __restrict__ nbr,   // [B,M,32] int64 or int32
    float* __restrict__ out)         // [B,M,16]
{
    // per-warp layer-1 table: {W1[0][j], W1[1][j], c_j, 0} with
    // c_j = b1[j] + x0*W1[2][j] + x1*W1[3][j]   (x is warp-uniform)
    __shared__ __align__(16) float4 sL1[8][HID];        // 8 KB

    const int tid  = threadIdx.x;
    const int wb   = tid >> 5;
    const int lane = tid & 31;
    const int warp = (blockIdx.x << 3) + wb;   // global (b,m) id
    const int b    = warp / MM;

    // ---- per-lane gather ----
    const bool is64 = (g_idx_is64 != 0);
    long long raw;
    if (is64) raw = ((const long long*)nbr)[(size_t)warp * KNB + lane];
    else      raw = (long long)((const int*)nbr)[(size_t)warp * KNB + lane];
    const bool valid = (raw >= 0);
    const int idx = valid ? (int)raw : 0;

    const float2 yy = ((const float2*)y)[(size_t)b * NN + idx];
    const float2 xx = ((const float2*)x)[warp];
    const float a0 = yy.x, a1 = yy.y;
    const float s = valid ? wts[(size_t)b * NN + idx] : 0.0f;

    // ---- build per-warp layer-1 table (2 j's per lane) ----
    {
        const float a2 = xx.x, a3 = xx.y;
        #pragma unroll
        for (int t = 0; t < 2; t++) {
            int j = lane + 32 * t;
            float w0 = W1[j];
            float w1 = W1[HID + j];
            float w2 = W1[2 * HID + j];
            float w3 = W1[3 * HID + j];
            float c  = fmaf(a3, w3, fmaf(a2, w2, b1[j]));
            sL1[wb][j] = make_float4(w0, w1, c, 0.0f);
        }
    }
    __syncthreads();

    // ---- MLP mainloop: layer-2 weights from the constant port (no L1TEX) ----
    unsigned long long acc2[8];
    #pragma unroll
    for (int p = 0; p < 8; p++) acc2[p] = 0ull;

    #pragma unroll 8
    for (int j = 0; j < HID; j++) {
        float4 v = sL1[wb][j];
        float h = fmaf(a0, v.x, fmaf(a1, v.y, v.z));
        float g = gelu_fast(h);
        unsigned long long gg = pack2(g, g);
        const ulonglong2* w2p = (const ulonglong2*)&cW2[j * DOUT];
        ulonglong2 wA = w2p[0], wB = w2p[1], wC = w2p[2], wD = w2p[3];
        acc2[0] = fmax2(gg, wA.x, acc2[0]);
        acc2[1] = fmax2(gg, wA.y, acc2[1]);
        acc2[2] = fmax2(gg, wB.x, acc2[2]);
        acc2[3] = fmax2(gg, wB.y, acc2[3]);
        acc2[4] = fmax2(gg, wC.x, acc2[4]);
        acc2[5] = fmax2(gg, wC.y, acc2[5]);
        acc2[6] = fmax2(gg, wD.x, acc2[6]);
        acc2[7] = fmax2(gg, wD.y, acc2[7]);
    }

    // ---- epilogue scale: (acc + b2) * f_y[idx] * w[idx] * valid, packed ----
    {
        const ulonglong2* fyp = (const ulonglong2*)(f_y + ((size_t)b * NN + idx) * DOUT);
        const ulonglong2* b2p = (const ulonglong2*)cb2;
        unsigned long long ss = pack2(s, s);
        #pragma unroll
        for (int q = 0; q < 4; q++) {
            ulonglong2 fy = fyp[q];
            ulonglong2 bq = b2p[q];
            acc2[2 * q + 0] = mulx2(mulx2(addx2(acc2[2 * q + 0], bq.x), fy.x), ss);
            acc2[2 * q + 1] = mulx2(mulx2(addx2(acc2[2 * q + 1], bq.y), fy.y), ss);
        }
    }

    // ---- channel-splitting warp reduce (16 ch over 32 lanes) ----
    {
        bool hi = (lane & 16) != 0;
        #pragma unroll
        for (int p = 0; p < 4; p++) {
            unsigned long long send = hi ? acc2[p]     : acc2[p + 4];
            unsigned long long keep = hi ? acc2[p + 4] : acc2[p];
            acc2[p] = addx2(keep, shfl64(send, 16));
        }
    }
    {
        bool hi = (lane & 8) != 0;
        #pragma unroll
        for (int p = 0; p < 2; p++) {
            unsigned long long send = hi ? acc2[p]     : acc2[p + 2];
            unsigned long long keep = hi ? acc2[p + 2] : acc2[p];
            acc2[p] = addx2(keep, shfl64(send, 8));
        }
    }
    {
        bool hi = (lane & 4) != 0;
        unsigned long long send = hi ? acc2[0] : acc2[1];
        unsigned long long keep = hi ? acc2[1] : acc2[0];
        acc2[0] = addx2(keep, shfl64(send, 4));
    }
    float r;
    {
        float lo, hv;
        unpack2(acc2[0], lo, hv);
        bool hi = (lane & 2) != 0;
        float send = hi ? lo : hv;
        float keep = hi ? hv : lo;
        r = keep + __shfl_xor_sync(0xffffffffu, send, 2);
    }
    r += __shfl_xor_sync(0xffffffffu, r, 1);

    if ((lane & 1) == 0)
        out[(size_t)warp * DOUT + (lane >> 1)] = r;
}

extern "C" void kernel_launch(void* const* d_in, const int* in_sizes, int n_in,
                              void* d_out, int out_size) {
    const float* y   = (const float*)d_in[0];
    const float* x   = (const float*)d_in[1];
    const float* f_y = (const float*)d_in[2];
    const float* wts = (const float*)d_in[3];
    const float* W1  = (const float*)d_in[4];
    const float* b1  = (const float*)d_in[5];
    const float* W2  = (const float*)d_in[6];
    const float* b2  = (const float*)d_in[7];
    const void*  nbr = d_in[8];

    // Stage layer-2 weights into constant memory (D2D memcpy: capture-legal,
    // allocation-free). Ordered before the kernels on the same stream.
    cudaMemcpyToSymbolAsync(cW2, W2, HID * DOUT * sizeof(float), 0,
                            cudaMemcpyDeviceToDevice, 0);
    cudaMemcpyToSymbolAsync(cb2, b2, DOUT * sizeof(float), 0,
                            cudaMemcpyDeviceToDevice, 0);

    detect_idx_width_kernel<<<1, 1>>>((const int*)nbr);
    it_kernel<<<4096, 256>>>(y, x, f_y, wts, W1, b1, nbr, (float*)d_out);
}

// round 6
// speedup vs baseline: 1.4664x; 1.0680x over previous
#include <cuda_runtime.h>

#define BB   8
#define NN   9225
#define MM   4096
#define KNB  32
#define HID  64
#define DOUT 16

__device__ int g_idx_is64;

__constant__ __align__(16) float cW2[HID * DOUT];   // 4 KB
__constant__ __align__(16) float cb2[DOUT];

// Detect whether neighbors_index is int64 or int32 (branch-free: loads overlap).
__global__ void detect_idx_width_kernel(const int* __restrict__ nbr) {
    int bad = 0;
    #pragma unroll
    for (int i = 0; i < 64; i++) {
        int hi = nbr[2 * i + 1];
        bad |= (hi != 0 && hi != -1);
    }
    g_idx_is64 = bad ? 0 : 1;
}

// ---- packed f32x2 helpers (sm_103a FFMA2 path, PTX-only) ----
typedef unsigned long long u64;
__device__ __forceinline__ u64 fmax2(u64 a, u64 b, u64 c) {
    u64 r;
    asm("fma.rn.f32x2 %0, %1, %2, %3;" : "=l"(r) : "l"(a), "l"(b), "l"(c));
    return r;
}
__device__ __forceinline__ u64 addx2(u64 a, u64 b) {
    u64 r;
    asm("add.rn.f32x2 %0, %1, %2;" : "=l"(r) : "l"(a), "l"(b));
    return r;
}
__device__ __forceinline__ u64 mulx2(u64 a, u64 b) {
    u64 r;
    asm("mul.rn.f32x2 %0, %1, %2;" : "=l"(r) : "l"(a), "l"(b));
    return r;
}
__device__ __forceinline__ u64 pack2(float lo, float hi) {
    u64 r;
    asm("mov.b64 %0, {%1, %2};" : "=l"(r) : "f"(lo), "f"(hi));
    return r;
}
__device__ __forceinline__ void unpack2(u64 v, float& lo, float& hi) {
    asm("mov.b64 {%0, %1}, %2;" : "=f"(lo), "=f"(hi) : "l"(v));
}
__device__ __forceinline__ u64 shfl64(u64 v, int off) {
    return __shfl_xor_sync(0xffffffffu, v, off);
}
__device__ __forceinline__ float rcp_approx(float x) {
    float r;
    asm("rcp.approx.f32 %0, %1;" : "=f"(r) : "f"(x));
    return r;
}
__device__ __forceinline__ float ex2_approx(float x) {
    float r;
    asm("ex2.approx.f32 %0, %1;" : "=f"(r) : "f"(x));
    return r;
}

__global__ __launch_bounds__(256) void it_kernel(
    const float* __restrict__ y,     // [B,N,2]
    const float* __restrict__ x,     // [B,M,2]
    const float* __restrict__ f_y,   // [B,N,16]
    const float* __restrict__ wts,   // [B,N]
    const float* __restrict__ W1,    // [4,64]
    const float* __restrict__ b1,    // [64]
    const void*  __restrict__ nbr,   // [B,M,32] int64 or int32
    float* __restrict__ out)         // [B,M,16]
{
    // Per-warp layer-1 table, PRE-SCALED by 1/sqrt(2) and packed by hidden
    // pair (j, j+32): sW01 = {w0_j|w0_j32, w1_j|w1_j32}, sC = {c_j|c_j32},
    // where c_j = b1_j + x0*W1[2][j] + x1*W1[3][j] (x warp-uniform).
    // Mainloop then computes h' = h/sqrt(2) = erf argument directly.
    __shared__ __align__(16) ulonglong2 sW01[8][32];   // 4 KB
    __shared__ __align__(8)  u64        sC[8][32];     // 2 KB

    const int tid  = threadIdx.x;
    const int wb   = tid >> 5;
    const int lane = tid & 31;
    const int warp = (blockIdx.x << 3) + wb;   // global (b,m) id
    const int b    = warp / MM;

    // ---- per-lane gather ----
    const bool is64 = (g_idx_is64 != 0);
    long long raw;
    if (is64) raw = ((const long long*)nbr)[(size_t)warp * KNB + lane];
    else      raw = (long long)((const int*)nbr)[(size_t)warp * KNB + lane];
    const bool valid = (raw >= 0);
    const int idx = valid ? (int)raw : 0;

    const float2 yy = ((const float2*)y)[(size_t)b * NN + idx];
    const float2 xx = ((const float2*)x)[warp];
    const float s = valid ? wts[(size_t)b * NN + idx] : 0.0f;

    // ---- build packed pre-scaled layer-1 table (pair `lane` per lane) ----
    {
        const float ISQ2 = 0.70710678118654752f;
        const float a2 = xx.x, a3 = xx.y;
        int j0 = lane, j1 = lane + 32;
        float w0a = W1[j0] * ISQ2,          w0b = W1[j1] * ISQ2;
        float w1a = W1[HID + j0] * ISQ2,    w1b = W1[HID + j1] * ISQ2;
        float ca = fmaf(a3, W1[3 * HID + j0], fmaf(a2, W1[2 * HID + j0], b1[j0])) * ISQ2;
        float cb = fmaf(a3, W1[3 * HID + j1], fmaf(a2, W1[2 * HID + j1], b1[j1])) * ISQ2;
        ulonglong2 w01;
        w01.x = pack2(w0a, w0b);
        w01.y = pack2(w1a, w1b);
        sW01[wb][lane] = w01;
        sC[wb][lane] = pack2(ca, cb);
    }
    __syncthreads();

    // packed broadcast inputs / constants
    const u64 a0p  = pack2(yy.x, yy.x);
    const u64 a1p  = pack2(yy.y, yy.y);
    const u64 ONES = 0x3f8000003f800000ull;               // {1,1}
    const u64 CA   = pack2(0.3275911f, 0.3275911f);
    const u64 NL2E = pack2(-1.4426950408889634f, -1.4426950408889634f);
    const u64 CH   = pack2(0.70710678118654752f, 0.70710678118654752f); // h = h'*sqrt2; 0.5h = h'*0.7071
    const u64 QC4  = pack2(-1.061405429f, -1.061405429f); // negated A-S coeffs
    const u64 QC3  = pack2( 1.453152027f,  1.453152027f);
    const u64 QC2  = pack2(-1.421413741f, -1.421413741f);
    const u64 QC1  = pack2( 0.284496736f,  0.284496736f);
    const u64 QC0  = pack2(-0.254829592f, -0.254829592f);
    const u64 ABSM = 0x7fffffff7fffffffull;

    u64 acc2[8];
    #pragma unroll
    for (int p = 0; p < 8; p++) acc2[p] = 0ull;

    #pragma unroll 4
    for (int p = 0; p < 32; p++) {
        ulonglong2 w01 = sW01[wb][p];
        u64 cp = sC[wb][p];
        // h' = erf argument for hidden units (p, p+32)
        u64 hp = fmax2(a0p, w01.x, fmax2(a1p, w01.y, cp));
        // branchless A-S erf, packed
        u64 ax  = hp & ABSM;                          // |x|
        u64 d   = fmax2(CA, ax, ONES);
        float dlo, dhi; unpack2(d, dlo, dhi);
        u64 t   = pack2(rcp_approx(dlo), rcp_approx(dhi));
        u64 aa  = mulx2(hp, hp);                      // x^2 (even: no abs)
        u64 arg = mulx2(aa, NL2E);
        float alo, ahi; unpack2(arg, alo, ahi);
        u64 e   = pack2(ex2_approx(alo), ex2_approx(ahi));
        u64 q   = fmax2(QC4, t, QC3);
        q = fmax2(q, t, QC2);
        q = fmax2(q, t, QC1);
        q = fmax2(q, t, QC0);
        u64 qt  = mulx2(q, t);
        u64 r   = fmax2(qt, e, ONES);                 // erf(|x|) = 1 - P*t*e
        u64 hh  = mulx2(hp, CH);                      // 0.5*h
        u64 ahh = hh & ABSM;
        u64 g   = fmax2(ahh, r, hh);                  // gelu(h)
        // split the pair back to two broadcast factors
        float glo, ghi; unpack2(g, glo, ghi);
        u64 gl = pack2(glo, glo);
        u64 gh = pack2(ghi, ghi);
        // layer 2: unit p and unit p+32
        const ulonglong2* wlo = (const ulonglong2*)&cW2[p * DOUT];
        const ulonglong2* whi = (const ulonglong2*)&cW2[(p + 32) * DOUT];
        ulonglong2 lA = wlo[0], lB = wlo[1], lC = wlo[2], lD = wlo[3];
        acc2[0] = fmax2(gl, lA.x, acc2[0]);
        acc2[1] = fmax2(gl, lA.y, acc2[1]);
        acc2[2] = fmax2(gl, lB.x, acc2[2]);
        acc2[3] = fmax2(gl, lB.y, acc2[3]);
        acc2[4] = fmax2(gl, lC.x, acc2[4]);
        acc2[5] = fmax2(gl, lC.y, acc2[5]);
        acc2[6] = fmax2(gl, lD.x, acc2[6]);
        acc2[7] = fmax2(gl, lD.y, acc2[7]);
        ulonglong2 hA = whi[0], hB = whi[1], hC = whi[2], hD = whi[3];
        acc2[0] = fmax2(gh, hA.x, acc2[0]);
        acc2[1] = fmax2(gh, hA.y, acc2[1]);
        acc2[2] = fmax2(gh, hB.x, acc2[2]);
        acc2[3] = fmax2(gh, hB.y, acc2[3]);
        acc2[4] = fmax2(gh, hC.x, acc2[4]);
        acc2[5] = fmax2(gh, hC.y, acc2[5]);
        acc2[6] = fmax2(gh, hD.x, acc2[6]);
        acc2[7] = fmax2(gh, hD.y, acc2[7]);
    }

    // ---- epilogue scale: (acc + b2) * f_y[idx] * w[idx] * valid, packed ----
    {
        const ulonglong2* fyp = (const ulonglong2*)(f_y + ((size_t)b * NN + idx) * DOUT);
        const ulonglong2* b2p = (const ulonglong2*)cb2;
        u64 ss = pack2(s, s);
        #pragma unroll
        for (int q2 = 0; q2 < 4; q2++) {
            ulonglong2 fy = fyp[q2];
            ulonglong2 bq = b2p[q2];
            acc2[2 * q2 + 0] = mulx2(mulx2(addx2(acc2[2 * q2 + 0], bq.x), fy.x), ss);
            acc2[2 * q2 + 1] = mulx2(mulx2(addx2(acc2[2 * q2 + 1], bq.y), fy.y), ss);
        }
    }

    // ---- channel-splitting warp reduce (16 ch over 32 lanes) ----
    {
        bool hi = (lane & 16) != 0;
        #pragma unroll
        for (int p = 0; p < 4; p++) {
            u64 send = hi ? acc2[p]     : acc2[p + 4];
            u64 keep = hi ? acc2[p + 4] : acc2[p];
            acc2[p] = addx2(keep, shfl64(send, 16));
        }
    }
    {
        bool hi = (lane & 8) != 0;
        #pragma unroll
        for (int p = 0; p < 2; p++) {
            u64 send = hi ? acc2[p]     : acc2[p + 2];
            u64 keep = hi ? acc2[p + 2] : acc2[p];
            acc2[p] = addx2(keep, shfl64(send, 8));
        }
    }
    {
        bool hi = (lane & 4) != 0;
        u64 send = hi ? acc2[0] : acc2[1];
        u64 keep = hi ? acc2[1] : acc2[0];
        acc2[0] = addx2(keep, shfl64(send, 4));
    }
    float r;
    {
        float lo, hv;
        unpack2(acc2[0], lo, hv);
        bool hi = (lane & 2) != 0;
        float send = hi ? lo : hv;
        float keep = hi ? hv : lo;
        r = keep + __shfl_xor_sync(0xffffffffu, send, 2);
    }
    r += __shfl_xor_sync(0xffffffffu, r, 1);

    if ((lane & 1) == 0)
        out[(size_t)warp * DOUT + (lane >> 1)] = r;
}

extern "C" void kernel_launch(void* const* d_in, const int* in_sizes, int n_in,
                              void* d_out, int out_size) {
    const float* y   = (const float*)d_in[0];
    const float* x   = (const float*)d_in[1];
    const float* f_y = (const float*)d_in[2];
    const float* wts = (const float*)d_in[3];
    const float* W1  = (const float*)d_in[4];
    const float* b1  = (const float*)d_in[5];
    const float* W2  = (const float*)d_in[6];
    const float* b2  = (const float*)d_in[7];
    const void*  nbr = d_in[8];

    cudaMemcpyToSymbolAsync(cW2, W2, HID * DOUT * sizeof(float), 0,
                            cudaMemcpyDeviceToDevice, 0);
    cudaMemcpyToSymbolAsync(cb2, b2, DOUT * sizeof(float), 0,
                            cudaMemcpyDeviceToDevice, 0);

    detect_idx_width_kernel<<<1, 1>>>((const int*)nbr);
    it_kernel<<<4096, 256>>>(y, x, f_y, wts, W1, b1, nbr, (float*)d_out);
}